// round 14
// baseline (speedup 1.0000x reference)
#include <cuda_runtime.h>
#include <cuda_fp16.h>
#include <cstdint>

#define T_SEQ   512
#define B_DIM   256
#define H_DIM   256
#define E_DIM   6
#define C_DIM   10
#define CLUSTER 4
#define G_COLS  8
#define NTHREADS 512
#define KC_N    16                  // 16 k-chunks of 16 -> K = 256 (h only)

// B: per column 132 words, fp16x2 per k-pair kp (0..127 = h, 128..131 pad)
//   stride 132 = 4 (mod 32) -> conflict-free LDS.32 across (g, tg)
#define SHI_W   132
#define B_MAT   (G_COLS * SHI_W * 4)             // 4224 B
#define OFF_BH   0                               // 2 ping-pong buffers (8448)
#define OFF_XB   (2 * B_MAT)                     // 8448 : x staged [t][col] (16384)
#define OFF_EMBF (OFF_XB + T_SEQ * G_COLS * 4)   // 24832 : emb fp32 [10][6] (240)
#define OFF_WXS  (OFF_EMBF + 240)                // 25072 : Wx fp32 [64][4][6] (6144)
#define OFF_BSH  (OFF_WXS + 6144)                // 31216 : bias fp32 [4][8] (128)
#define OFF_MB   (OFF_BSH + 128)                 // 31344 : mbar [2] (16 B)
#define SMEM_BYTES (OFF_MB + 16 + 16)
#define MB_COUNT 64u                // 16 warps x 4 CTAs arrivals per phase

__device__ __forceinline__ uint32_t smem_u32(const void* p) {
    return (uint32_t)__cvta_generic_to_shared(p);
}
__device__ __forceinline__ uint32_t mapa_rank(uint32_t addr, int r) {
    uint32_t ret;
    asm("mapa.shared::cluster.u32 %0, %1, %2;" : "=r"(ret) : "r"(addr), "r"(r));
    return ret;
}
__device__ __forceinline__ void st_cluster_u32(uint32_t addr, uint32_t v) {
    asm volatile("st.shared::cluster.u32 [%0], %1;" :: "r"(addr), "r"(v) : "memory");
}
__device__ __forceinline__ void cluster_sync_() {
    asm volatile("barrier.cluster.arrive.aligned;\n\tbarrier.cluster.wait.aligned;" ::: "memory");
}
__device__ __forceinline__ void mbar_init(uint32_t addr, uint32_t cnt) {
    asm volatile("mbarrier.init.shared.b64 [%0], %1;" :: "r"(addr), "r"(cnt) : "memory");
}
__device__ __forceinline__ void mbar_arrive_cluster(uint32_t addr) {
    asm volatile("mbarrier.arrive.release.cluster.shared::cluster.b64 _, [%0];"
                 :: "r"(addr) : "memory");
}
__device__ __forceinline__ void mbar_wait(uint32_t addr, uint32_t parity) {
    asm volatile("{\n\t.reg .pred P;\n\tWL_%=:\n\t"
                 "mbarrier.try_wait.parity.acquire.cluster.shared::cta.b64 P, [%0], %1, 0x989680;\n\t"
                 "@!P bra WL_%=;\n\t}" :: "r"(addr), "r"(parity) : "memory");
}
__device__ __forceinline__ void mma16816h(float c[4], const uint32_t a[4],
                                          uint32_t b0, uint32_t b1) {
    asm volatile("mma.sync.aligned.m16n8k16.row.col.f32.f16.f16.f32 "
                 "{%0,%1,%2,%3}, {%4,%5,%6,%7}, {%8,%9}, {%0,%1,%2,%3};"
                 : "+f"(c[0]), "+f"(c[1]), "+f"(c[2]), "+f"(c[3])
                 : "r"(a[0]), "r"(a[1]), "r"(a[2]), "r"(a[3]), "r"(b0), "r"(b1));
}
__device__ __forceinline__ uint32_t pack_h2(float a, float b) {
    __half2 t = __floats2half2_rn(a, b);
    return *(uint32_t*)&t;
}
__device__ __forceinline__ float tanhapx(float x) {
    float y;
    asm("tanh.approx.f32 %0, %1;" : "=f"(y) : "f"(x));
    return y;
}
__device__ __forceinline__ float sigapx(float x) {
    return fmaf(0.5f, tanhapx(0.5f * x), 0.5f);
}

extern "C" __global__ void __launch_bounds__(NTHREADS, 1) __cluster_dims__(CLUSTER, 1, 1)
lstm_hmma_kernel(const int* __restrict__ x, const float* __restrict__ emb,
                 const float* __restrict__ Wxg, const float* __restrict__ Whg, const float* __restrict__ bg,
                 const float* __restrict__ Wxi, const float* __restrict__ Whi, const float* __restrict__ bi,
                 const float* __restrict__ Wxf, const float* __restrict__ Whf, const float* __restrict__ bf,
                 const float* __restrict__ Wxo, const float* __restrict__ Who, const float* __restrict__ bo,
                 const float* __restrict__ Wp,  const float* __restrict__ bp,
                 float* __restrict__ out)
{
    extern __shared__ char sb[];
    int*   xbuf = (int*)(sb + OFF_XB);
    float* embf = (float*)(sb + OFF_EMBF);
    float* wxs  = (float*)(sb + OFF_WXS);     // [j][gate][e]
    float* bsh  = (float*)(sb + OFF_BSH);     // [gate][col]
    const uint32_t sb32 = smem_u32(sb);

    const int tid  = threadIdx.x;
    const int wid  = tid >> 5;        // 0..15, one m16n8 tile per warp
    const int lane = tid & 31;
    const int g    = lane >> 2;       // groupID 0..7
    const int tg   = lane & 3;        // thread-in-group
    const int qa   = g >> 2;          // gate-pair selector
    const int rank = blockIdx.x & (CLUSTER - 1);
    const int cid  = blockIdx.x / CLUSTER;
    const int col0 = cid * G_COLS;

    const float* WhTab[4] = { Whg, Whi, Whf, Who };
    const float* WxTab[4] = { Wxg, Wxi, Wxf, Wxo };
    const float* bTab[4]  = { bg,  bi,  bf,  bo  };

    // ---- A fragments: Wh fp16, remapped rows ----
    // warp tile row r (0..15): gate = r>>2, j = 4*wid + (r&3)  (j = 0..63)
    uint32_t aHi[KC_N][4];
    {
        auto getA = [&](int r, int k) -> float {
            int gate = r >> 2, j = 4 * wid + (r & 3);
            return WhTab[gate][(rank * 64 + j) * H_DIM + k];
        };
        const int ra = g, rb = g + 8;
        #pragma unroll
        for (int kc = 0; kc < KC_N; kc++) {
            const int k0 = kc * 16 + 2 * tg;
            aHi[kc][0] = pack_h2(getA(ra, k0),     getA(ra, k0 + 1));
            aHi[kc][1] = pack_h2(getA(rb, k0),     getA(rb, k0 + 1));
            aHi[kc][2] = pack_h2(getA(ra, k0 + 8), getA(ra, k0 + 9));
            aHi[kc][3] = pack_h2(getA(rb, k0 + 8), getA(rb, k0 + 9));
        }
    }

    // thread-owned output mapping
    const int jloc = 4 * wid + (g & 3);          // 0..63
    const int cA   = 2 * tg + qa;                // owned column 0..7
    const int jlow = ((g & 1) == 0);
    const int kpl  = 2 * wid + ((g & 3) >> 1);   // j>>1, 0..31
    const uint32_t stCol = (uint32_t)((cA * SHI_W + rank * 32 + kpl) * 4);

    // ---- smem init: B zero, x staged, emb, Wx, bias, mbarriers ----
    for (int i = tid; i < (2 * B_MAT) / 4; i += NTHREADS)
        ((uint32_t*)(sb + OFF_BH))[i] = 0u;
    for (int i = tid; i < G_COLS * T_SEQ; i += NTHREADS) {
        int c = i >> 9, t = i & 511;
        xbuf[t * G_COLS + c] = x[(col0 + c) * T_SEQ + t];
    }
    if (tid < 10 * E_DIM) embf[tid] = emb[tid];
    for (int i = tid; i < 64 * 4 * E_DIM; i += NTHREADS) {
        int j = i / (4 * E_DIM), rr = i % (4 * E_DIM);
        int q = rr / E_DIM, e = rr % E_DIM;
        wxs[i] = WxTab[q][(rank * 64 + j) * E_DIM + e];
    }
    if (tid < 32) {
        int q = tid >> 3, c = tid & 7;
        bsh[tid] = bTab[q][col0 + c];
    }
    if (tid == 0) {
        mbar_init(sb32 + OFF_MB,     MB_COUNT);
        mbar_init(sb32 + OFF_MB + 8, MB_COUNT);
    }

    uint32_t peerA, peerB, mbarR;   // store targets + this lane's arrive target base
    {
        uint32_t pr[CLUSTER];
        #pragma unroll
        for (int r = 0; r < CLUSTER; r++) pr[r] = mapa_rank(sb32, r);
        peerA = jlow ? pr[0] : pr[2];
        peerB = jlow ? pr[1] : pr[3];
        mbarR = pr[lane & 3] + OFF_MB;   // lanes 0-3 arrive to peers 0-3
    }

    __syncthreads();
    cluster_sync_();                 // mbar init visible before any arrive

    const uint32_t coff = (uint32_t)(g * SHI_W * 4);
    float cst = 0.0f;

    int p = 0;
    for (int t = 0; t < T_SEQ; t++) {
        // ---- preX: bias + Wx*x_t for (jloc, cA) — overlaps wait ----
        int xi = xbuf[t * G_COLS + cA];
        const float* ev = embf + xi * E_DIM;
        const float* wxr = wxs + jloc * (4 * E_DIM);
        float pX[4];
        #pragma unroll
        for (int q = 0; q < 4; q++) pX[q] = bsh[q * 8 + cA];
        #pragma unroll
        for (int e = 0; e < E_DIM; e++) {
            float ee = ev[e];
            #pragma unroll
            for (int q = 0; q < 4; q++)
                pX[q] = fmaf(wxr[q * E_DIM + e], ee, pX[q]);
        }

        // ---- wait for buffer p: all step-(t-1) stores arrived + reads done ----
        if (t > 0)
            mbar_wait(sb32 + OFF_MB + p * 8, (uint32_t)(((t - 1) >> 1) & 1));

        // ---- MMA: 16 chunks, 2 independent chains of 8 ----
        const char* Bp = sb + OFF_BH + p * B_MAT;
        float h0[4] = {0,0,0,0}, h1[4] = {0,0,0,0};
        #pragma unroll
        for (int kc = 0; kc < 8; kc++) {
            const uint32_t kbA = (uint32_t)(8 * kc + tg) * 4;
            const uint32_t kbB = (uint32_t)(8 * (kc + 8) + tg) * 4;
            uint32_t A0 = *(const uint32_t*)(Bp + coff + kbA);
            uint32_t A1 = *(const uint32_t*)(Bp + coff + kbA + 16);
            uint32_t B0 = *(const uint32_t*)(Bp + coff + kbB);
            uint32_t B1 = *(const uint32_t*)(Bp + coff + kbB + 16);
            mma16816h(h0, aHi[kc],     A0, A1);
            mma16816h(h1, aHi[kc + 8], B0, B1);
        }
        float d0 = h0[0] + h1[0];    // (gate qa,   col 2tg)
        float d1 = h0[1] + h1[1];    // (gate qa,   col 2tg+1)
        float d2 = h0[2] + h1[2];    // (gate qa+2, col 2tg)
        float d3 = h0[3] + h1[3];    // (gate qa+2, col 2tg+1)

        // ---- gate exchange with lane^16 (same j, other gate-pair) ----
        float sA = qa ? d0 : d1;
        float rA = __shfl_xor_sync(0xffffffffu, sA, 16);
        float sB = qa ? d2 : d3;
        float rB = __shfl_xor_sync(0xffffffffu, sB, 16);
        float pg0 = (qa ? rA : d0) + pX[0];   // gate g
        float pg1 = (qa ? d1 : rA) + pX[1];   // gate i
        float pg2 = (qa ? rB : d2) + pX[2];   // gate f
        float pg3 = (qa ? d3 : rB) + pX[3];   // gate o

        // ---- activations + c/h update for (jloc, cA) ----
        float gg = tanhapx(pg0), ii = sigapx(pg1), ff = sigapx(pg2), oo = sigapx(pg3);
        cst = fmaf(gg, ii, cst * ff);
        const float hv = tanhapx(cst) * oo;

        // ---- j-pair exchange with lane^4: (even j, odd j) same col ----
        float ov = __shfl_xor_sync(0xffffffffu, hv, 4);
        float va = jlow ? hv : ov;    // k even
        float vb = jlow ? ov : hv;    // k odd
        const uint32_t pkt = pack_h2(va, vb);

        // ---- store pkt to 2 of 4 peers (partner covers the other 2) ----
        const uint32_t dOff = (uint32_t)(OFF_BH + (p ^ 1) * B_MAT) + stCol;
        st_cluster_u32(peerA + dOff, pkt);
        st_cluster_u32(peerB + dOff, pkt);

        // ---- signal: syncwarp (HB edge over all lanes' stores), then
        //      lanes 0-3 release-arrive on the 4 peers' mbar[p^1] ----
        __syncwarp();
        if (lane < 4)
            mbar_arrive_cluster(mbarR + (uint32_t)((p ^ 1) * 8));

        p ^= 1;
    }

    // drain: stores at t=511 went into B[0]; its 256th completion has parity 1
    mbar_wait(sb32 + OFF_MB, 1u);

    // ---- projection: out[b, c] = sum_k Wp[c,k] h[k,b] + bp[c] (final h in B[0]) ----
    if (rank == 0 && tid < G_COLS * C_DIM) {
        const int col = tid / C_DIM;
        const int cls = tid % C_DIM;
        const uint32_t* Bc = (const uint32_t*)(sb + OFF_BH) + col * SHI_W;
        const float* wpr = Wp + cls * H_DIM;
        float s = bp[cls];
        for (int kp = 0; kp < H_DIM / 2; kp++) {
            uint32_t w = Bc[kp];
            __half2 hw = *(__half2*)&w;
            s = fmaf(wpr[2 * kp],     __half2float(hw.x),
                fmaf(wpr[2 * kp + 1], __half2float(hw.y), s));
        }
        out[(col0 + col) * C_DIM + cls] = s;
    }
}

extern "C" void kernel_launch(void* const* d_in, const int* in_sizes, int n_in,
                              void* d_out, int out_size) {
    (void)in_sizes; (void)n_in; (void)out_size;
    const int*   x   = (const int*)  d_in[0];
    const float* emb = (const float*)d_in[1];
    const float* Wxg = (const float*)d_in[2];
    const float* Whg = (const float*)d_in[3];
    const float* bg  = (const float*)d_in[4];
    const float* Wxi = (const float*)d_in[5];
    const float* Whi = (const float*)d_in[6];
    const float* bi  = (const float*)d_in[7];
    const float* Wxf = (const float*)d_in[8];
    const float* Whf = (const float*)d_in[9];
    const float* bf  = (const float*)d_in[10];
    const float* Wxo = (const float*)d_in[11];
    const float* Who = (const float*)d_in[12];
    const float* bo  = (const float*)d_in[13];
    const float* Wp  = (const float*)d_in[14];
    const float* bp  = (const float*)d_in[15];
    float* out = (float*)d_out;

    cudaFuncSetAttribute(lstm_hmma_kernel,
                         cudaFuncAttributeMaxDynamicSharedMemorySize, SMEM_BYTES);
    // 32 clusters of 4 CTAs = 128 CTAs
    lstm_hmma_kernel<<<(B_DIM / G_COLS) * CLUSTER, NTHREADS, SMEM_BYTES>>>(
        x, emb, Wxg, Whg, bg, Wxi, Whi, bi, Wxf, Whf, bf, Wxo, Who, bo, Wp, bp, out);
}

// round 15
// speedup vs baseline: 1.0752x; 1.0752x over previous
#include <cuda_runtime.h>
#include <cuda_fp16.h>
#include <cstdint>

#define T_SEQ   512
#define B_DIM   256
#define H_DIM   256
#define E_DIM   6
#define C_DIM   10
#define CLUSTER 4
#define G_COLS  8
#define NTHREADS 512
#define KC_N    16                  // 16 k-chunks of 16 -> K = 256 (h only)

// B: per column 136 words (stride ==8 mod 32 -> conflict-free paired LDS.64).
// Word layout: k-pair kp stored at word bw(kp) = (kp>>3)*8 + (kp&3)*2 + ((kp>>2)&1)
// so chunk kc's fragment pair (kp=8kc+tg, kp=8kc+4+tg) is one aligned uint2.
#define SHI_W   136
#define B_MAT   (G_COLS * SHI_W * 4)             // 4352 B
#define OFF_BH   0                               // 2 ping-pong buffers (8704)
#define OFF_XB   (2 * B_MAT)                     // 8704  : x staged [t][col] (16384)
#define OFF_PXT  (OFF_XB + T_SEQ * G_COLS * 4)   // 25088 : PXT [10][64][4] f32 (10240)
#define SMEM_BYTES (OFF_PXT + 10240 + 16)

__device__ __forceinline__ uint32_t smem_u32(const void* p) {
    return (uint32_t)__cvta_generic_to_shared(p);
}
__device__ __forceinline__ uint32_t mapa_rank(uint32_t addr, int r) {
    uint32_t ret;
    asm("mapa.shared::cluster.u32 %0, %1, %2;" : "=r"(ret) : "r"(addr), "r"(r));
    return ret;
}
__device__ __forceinline__ void st_cluster_u32(uint32_t addr, uint32_t v) {
    asm volatile("st.shared::cluster.u32 [%0], %1;" :: "r"(addr), "r"(v) : "memory");
}
__device__ __forceinline__ void cluster_sync_() {
    asm volatile("barrier.cluster.arrive.aligned;\n\tbarrier.cluster.wait.aligned;" ::: "memory");
}
#define CL_ARRIVE() asm volatile("barrier.cluster.arrive.aligned;" ::: "memory")
#define CL_WAIT()   asm volatile("barrier.cluster.wait.aligned;" ::: "memory")

__device__ __forceinline__ void mma16816h(float c[4], const uint32_t a[4],
                                          uint32_t b0, uint32_t b1) {
    asm volatile("mma.sync.aligned.m16n8k16.row.col.f32.f16.f16.f32 "
                 "{%0,%1,%2,%3}, {%4,%5,%6,%7}, {%8,%9}, {%0,%1,%2,%3};"
                 : "+f"(c[0]), "+f"(c[1]), "+f"(c[2]), "+f"(c[3])
                 : "r"(a[0]), "r"(a[1]), "r"(a[2]), "r"(a[3]), "r"(b0), "r"(b1));
}
__device__ __forceinline__ uint32_t pack_h2(float a, float b) {
    __half2 t = __floats2half2_rn(a, b);
    return *(uint32_t*)&t;
}
__device__ __forceinline__ float tanhapx(float x) {
    float y;
    asm("tanh.approx.f32 %0, %1;" : "=f"(y) : "f"(x));
    return y;
}
__device__ __forceinline__ float sigapx(float x) {
    return fmaf(0.5f, tanhapx(0.5f * x), 0.5f);
}
__device__ __host__ __forceinline__ int bw_kp(int kp) {
    return ((kp >> 3) << 3) + ((kp & 3) << 1) + ((kp >> 2) & 1);
}

extern "C" __global__ void __launch_bounds__(NTHREADS, 1) __cluster_dims__(CLUSTER, 1, 1)
lstm_hmma_kernel(const int* __restrict__ x, const float* __restrict__ emb,
                 const float* __restrict__ Wxg, const float* __restrict__ Whg, const float* __restrict__ bg,
                 const float* __restrict__ Wxi, const float* __restrict__ Whi, const float* __restrict__ bi,
                 const float* __restrict__ Wxf, const float* __restrict__ Whf, const float* __restrict__ bf,
                 const float* __restrict__ Wxo, const float* __restrict__ Who, const float* __restrict__ bo,
                 const float* __restrict__ Wp,  const float* __restrict__ bp,
                 float* __restrict__ out)
{
    extern __shared__ char sb[];
    int*    xbuf = (int*)(sb + OFF_XB);
    float4* pxt  = (float4*)(sb + OFF_PXT);   // [v*64 + j] -> 4 gates
    const uint32_t sb32 = smem_u32(sb);

    const int tid  = threadIdx.x;
    const int wid  = tid >> 5;        // 0..15, one m16n8 tile per warp
    const int lane = tid & 31;
    const int g    = lane >> 2;       // groupID 0..7
    const int tg   = lane & 3;        // thread-in-group
    const int qa   = g >> 2;          // gate-pair selector
    const int rank = blockIdx.x & (CLUSTER - 1);
    const int cid  = blockIdx.x / CLUSTER;
    const int col0 = cid * G_COLS;

    const float* WhTab[4] = { Whg, Whi, Whf, Who };
    const float* WxTab[4] = { Wxg, Wxi, Wxf, Wxo };
    const float* bTab[4]  = { bg,  bi,  bf,  bo  };

    // ---- A fragments: Wh fp16, remapped rows ----
    // warp tile row r (0..15): gate = r>>2, j = 4*wid + (r&3)  (j = 0..63)
    uint32_t aHi[KC_N][4];
    {
        auto getA = [&](int r, int k) -> float {
            int gate = r >> 2, j = 4 * wid + (r & 3);
            return WhTab[gate][(rank * 64 + j) * H_DIM + k];
        };
        const int ra = g, rb = g + 8;
        #pragma unroll
        for (int kc = 0; kc < KC_N; kc++) {
            const int k0 = kc * 16 + 2 * tg;
            aHi[kc][0] = pack_h2(getA(ra, k0),     getA(ra, k0 + 1));
            aHi[kc][1] = pack_h2(getA(rb, k0),     getA(rb, k0 + 1));
            aHi[kc][2] = pack_h2(getA(ra, k0 + 8), getA(ra, k0 + 9));
            aHi[kc][3] = pack_h2(getA(rb, k0 + 8), getA(rb, k0 + 9));
        }
    }

    // thread-owned output mapping
    const int jloc = 4 * wid + (g & 3);          // 0..63
    const int cA   = 2 * tg + qa;                // owned column 0..7
    const int jlow = ((g & 1) == 0);
    const int kpl  = 2 * wid + ((g & 3) >> 1);   // j>>1, 0..31
    const uint32_t stCol = (uint32_t)((cA * SHI_W + bw_kp(rank * 32 + kpl)) * 4);

    // bias in registers for the owned column
    float biasA[4];
    #pragma unroll
    for (int q = 0; q < 4; q++) biasA[q] = bTab[q][col0 + cA];

    // ---- smem init: B zero, x staged, PXT table ----
    for (int i = tid; i < (2 * B_MAT) / 4; i += NTHREADS)
        ((uint32_t*)(sb + OFF_BH))[i] = 0u;
    for (int i = tid; i < G_COLS * T_SEQ; i += NTHREADS) {
        int c = i >> 9, t = i & 511;
        xbuf[t * G_COLS + c] = x[(col0 + c) * T_SEQ + t];
    }
    // PXT[v][j][q] = sum_e Wx[q][(rank*64+j), e] * emb[v, e]
    for (int i = tid; i < 10 * 64; i += NTHREADS) {
        int v = i >> 6, j = i & 63;
        const float* ev = emb + v * E_DIM;
        float4 r;
        float* rp = (float*)&r;
        #pragma unroll
        for (int q = 0; q < 4; q++) {
            const float* wx = WxTab[q] + (rank * 64 + j) * E_DIM;
            float s = 0.0f;
            #pragma unroll
            for (int e = 0; e < E_DIM; e++) s = fmaf(wx[e], ev[e], s);
            rp[q] = s;
        }
        pxt[i] = r;
    }

    uint32_t peerA, peerB;   // this thread's two store targets
    {
        uint32_t pr[CLUSTER];
        #pragma unroll
        for (int r = 0; r < CLUSTER; r++) pr[r] = mapa_rank(sb32, r);
        peerA = jlow ? pr[0] : pr[2];
        peerB = jlow ? pr[1] : pr[3];
    }

    __syncthreads();
    cluster_sync_();
    CL_ARRIVE();                 // pairs with the wait at t=0

    const uint32_t coff = (uint32_t)(g * SHI_W * 4);
    float cst = 0.0f;

    int p = 0;
    for (int t = 0; t < T_SEQ; t++) {
        // ---- preX: bias + PXT lookup — overlaps barrier skew ----
        int xi = xbuf[t * G_COLS + cA];
        float4 px4 = pxt[xi * 64 + jloc];
        float pX[4];
        pX[0] = biasA[0] + px4.x;
        pX[1] = biasA[1] + px4.y;
        pX[2] = biasA[2] + px4.z;
        pX[3] = biasA[3] + px4.w;

        CL_WAIT();               // peers' stores visible; buffer p^1 reads done

        // ---- MMA: 16 chunks via paired LDS.64, 2 independent chains of 8 ----
        const char* Bp = sb + OFF_BH + p * B_MAT;
        float h0[4] = {0,0,0,0}, h1[4] = {0,0,0,0};
        #pragma unroll
        for (int kc = 0; kc < 8; kc++) {
            uint2 A = *(const uint2*)(Bp + coff + (uint32_t)(kc * 8 + tg * 2) * 4);
            uint2 B = *(const uint2*)(Bp + coff + (uint32_t)((kc + 8) * 8 + tg * 2) * 4);
            mma16816h(h0, aHi[kc],     A.x, A.y);
            mma16816h(h1, aHi[kc + 8], B.x, B.y);
        }
        float d0 = h0[0] + h1[0];    // (gate qa,   col 2tg)
        float d1 = h0[1] + h1[1];    // (gate qa,   col 2tg+1)
        float d2 = h0[2] + h1[2];    // (gate qa+2, col 2tg)
        float d3 = h0[3] + h1[3];    // (gate qa+2, col 2tg+1)

        // ---- gate exchange with lane^16 (same j, other gate-pair) ----
        float sA = qa ? d0 : d1;
        float rA = __shfl_xor_sync(0xffffffffu, sA, 16);
        float sB = qa ? d2 : d3;
        float rB = __shfl_xor_sync(0xffffffffu, sB, 16);
        float pg0 = (qa ? rA : d0) + pX[0];   // gate g
        float pg1 = (qa ? d1 : rA) + pX[1];   // gate i
        float pg2 = (qa ? rB : d2) + pX[2];   // gate f
        float pg3 = (qa ? d3 : rB) + pX[3];   // gate o

        // ---- activations + c/h update for (jloc, cA) ----
        float gg = tanhapx(pg0), ii = sigapx(pg1), ff = sigapx(pg2), oo = sigapx(pg3);
        cst = fmaf(gg, ii, cst * ff);
        const float hv = tanhapx(cst) * oo;

        // ---- j-pair exchange with lane^4: (even j, odd j) same col ----
        float ov = __shfl_xor_sync(0xffffffffu, hv, 4);
        float va = jlow ? hv : ov;    // k even
        float vb = jlow ? ov : hv;    // k odd
        const uint32_t pkt = pack_h2(va, vb);

        // ---- store pkt to 2 of 4 peers (partner covers the other 2) ----
        const uint32_t dOff = (uint32_t)(OFF_BH + (p ^ 1) * B_MAT) + stCol;
        st_cluster_u32(peerA + dOff, pkt);
        st_cluster_u32(peerB + dOff, pkt);

        CL_ARRIVE();             // release stores; consumed by peers' wait at t+1
        p ^= 1;
    }

    CL_WAIT();                   // t=511 stores (into B[0]) visible

    // ---- projection: out[b, c] = sum_k Wp[c,k] h[k,b] + bp[c] (final h in B[0]) ----
    if (rank == 0 && tid < G_COLS * C_DIM) {
        const int col = tid / C_DIM;
        const int cls = tid % C_DIM;
        const uint32_t* Bc = (const uint32_t*)(sb + OFF_BH) + col * SHI_W;
        const float* wpr = Wp + cls * H_DIM;
        float s = bp[cls];
        for (int kp = 0; kp < H_DIM / 2; kp++) {
            uint32_t w = Bc[bw_kp(kp)];
            __half2 hw = *(__half2*)&w;
            s = fmaf(wpr[2 * kp],     __half2float(hw.x),
                fmaf(wpr[2 * kp + 1], __half2float(hw.y), s));
        }
        out[(col0 + col) * C_DIM + cls] = s;
    }
}

extern "C" void kernel_launch(void* const* d_in, const int* in_sizes, int n_in,
                              void* d_out, int out_size) {
    (void)in_sizes; (void)n_in; (void)out_size;
    const int*   x   = (const int*)  d_in[0];
    const float* emb = (const float*)d_in[1];
    const float* Wxg = (const float*)d_in[2];
    const float* Whg = (const float*)d_in[3];
    const float* bg  = (const float*)d_in[4];
    const float* Wxi = (const float*)d_in[5];
    const float* Whi = (const float*)d_in[6];
    const float* bi  = (const float*)d_in[7];
    const float* Wxf = (const float*)d_in[8];
    const float* Whf = (const float*)d_in[9];
    const float* bf  = (const float*)d_in[10];
    const float* Wxo = (const float*)d_in[11];
    const float* Who = (const float*)d_in[12];
    const float* bo  = (const float*)d_in[13];
    const float* Wp  = (const float*)d_in[14];
    const float* bp  = (const float*)d_in[15];
    float* out = (float*)d_out;

    cudaFuncSetAttribute(lstm_hmma_kernel,
                         cudaFuncAttributeMaxDynamicSharedMemorySize, SMEM_BYTES);
    // 32 clusters of 4 CTAs = 128 CTAs
    lstm_hmma_kernel<<<(B_DIM / G_COLS) * CLUSTER, NTHREADS, SMEM_BYTES>>>(
        x, emb, Wxg, Whg, bg, Wxi, Whi, bi, Wxf, Whf, bf, Wxo, Who, bo, Wp, bp, out);
}